// round 9
// baseline (speedup 1.0000x reference)
#include <cuda_runtime.h>
#include <cuda_bf16.h>
#include <math.h>
#include <stdint.h>

#define SB   2048          // sequence length
#define NB   2             // batch
#define DD   1024          // model dim
#define HH   16            // heads
#define DH   64            // head dim
#define KSEL 16            // top-k tokens
#define MTOT (NB*SB)       // 4096 rows

typedef unsigned short u16;
typedef unsigned long long u64;

// ---------------- scratch (static device globals; no allocation) ----------------
__device__ float g_q[MTOT*DD];
__device__ float g_k[MTOT*DD];
__device__ float g_v[MTOT*DD];
__device__ float g_hidden[MTOT*(DD/2)];
__device__ float g_imp[MTOT];
__device__ int   g_idx[NB*KSEL];
__device__ int   g_sel[MTOT];
__device__ float g_ksel[NB*KSEL*DD];
__device__ float g_vsel[NB*KSEL*DD];

// bf16 hi/lo split arrays (weights in original [K][N] layout)
__device__ u16 g_xh[MTOT*DD],  g_xl[MTOT*DD];
__device__ u16 g_wqh[DD*DD],   g_wql[DD*DD];
__device__ u16 g_wkh[DD*DD],   g_wkl[DD*DD];
__device__ u16 g_wvh[DD*DD],   g_wvl[DD*DD];
__device__ u16 g_ws1h[DD*DD/2], g_ws1l[DD*DD/2];
__device__ u16 g_woh[DD*DD],   g_wol[DD*DD];
__device__ u16 g_ath[MTOT*DD], g_atl[MTOT*DD];

// ---------------- helpers ------------------------------------------------------
__device__ __forceinline__ void bsplit(float f, u16& h, u16& l) {
    __nv_bfloat16 hi = __float2bfloat16(f);
    h = __bfloat16_as_ushort(hi);
    l = __bfloat16_as_ushort(__float2bfloat16(f - __bfloat162float(hi)));
}

#define CPA16(dst, src) \
    asm volatile("cp.async.cg.shared.global [%0], [%1], 16;" :: "r"(dst), "l"(src))

#define LDSM4(r, addr) \
    asm volatile("ldmatrix.sync.aligned.m8n8.x4.shared.b16 {%0,%1,%2,%3}, [%4];" \
        : "=r"((r)[0]), "=r"((r)[1]), "=r"((r)[2]), "=r"((r)[3]) : "r"(addr))

#define LDSM4T(r, addr) \
    asm volatile("ldmatrix.sync.aligned.m8n8.x4.trans.shared.b16 {%0,%1,%2,%3}, [%4];" \
        : "=r"((r)[0]), "=r"((r)[1]), "=r"((r)[2]), "=r"((r)[3]) : "r"(addr))

#define MMA_BF16(d, a, b) \
    asm volatile("mma.sync.aligned.m16n8k16.row.col.f32.bf16.bf16.f32 " \
        "{%0,%1,%2,%3}, {%4,%5,%6,%7}, {%8,%9}, {%0,%1,%2,%3};" \
        : "+f"((d)[0]), "+f"((d)[1]), "+f"((d)[2]), "+f"((d)[3]) \
        : "r"((a)[0]), "r"((a)[1]), "r"((a)[2]), "r"((a)[3]), "r"((b)[0]), "r"((b)[1]))

// ---------------- fp32 -> bf16 hi/lo converters --------------------------------
__device__ __forceinline__ void conv_seg(const float* __restrict__ in,
                                         u16* __restrict__ h, u16* __restrict__ l,
                                         int n4, int idx, int stride)
{
    for (int i = idx; i < n4; i += stride) {
        float4 v = ((const float4*)in)[i];
        float f[4] = {v.x, v.y, v.z, v.w};
        u16 hb[4], lb[4];
        #pragma unroll
        for (int j = 0; j < 4; j++) bsplit(f[j], hb[j], lb[j]);
        *(uint2*)(h + (size_t)i * 4) = *(uint2*)hb;
        *(uint2*)(l + (size_t)i * 4) = *(uint2*)lb;
    }
}

__global__ void convert_inputs(const float* __restrict__ x,
                               const float* __restrict__ Wq,
                               const float* __restrict__ Wk,
                               const float* __restrict__ Wv,
                               const float* __restrict__ Ws1,
                               const float* __restrict__ Wo)
{
    const int idx = blockIdx.x * blockDim.x + threadIdx.x;
    const int stride = gridDim.x * blockDim.x;
    conv_seg(x,   g_xh,   g_xl,   MTOT*DD/4,  idx, stride);
    conv_seg(Wq,  g_wqh,  g_wql,  DD*DD/4,    idx, stride);
    conv_seg(Wk,  g_wkh,  g_wkl,  DD*DD/4,    idx, stride);
    conv_seg(Wv,  g_wvh,  g_wvl,  DD*DD/4,    idx, stride);
    conv_seg(Ws1, g_ws1h, g_ws1l, DD*(DD/2)/4, idx, stride);
    conv_seg(Wo,  g_woh,  g_wol,  DD*DD/4,    idx, stride);
}

// ---------------- bf16x3 tensor-core GEMM (fused multi-weight) -----------------
// C = A[M,K] @ W[K,N] + bias,  A,W split bf16 hi+lo: C = AhWh + AhWl + AlWh.
// 128x128 block tile, BK=32, 2-stage cp.async pipeline (dynamic smem),
// ldmatrix fragments, m16n8k16 mma. Grid.x selects weight segment.
struct Seg {
    const u16* wh;
    const u16* wl;
    const float* bias;
    float* c;
    int ldn;
    int relu;
};
struct Cfg { Seg s[4]; };

#define BKC   32
#define A_ROW 40     // 32 + 8 pad (halfs)
#define B_ROW 136    // 128 + 8 pad (halfs)
#define ASZ   (128*A_ROW*2)      // 10240 B
#define BSZ   (BKC*B_ROW*2)      // 8704 B
#define STAGEB (2*ASZ + 2*BSZ)   // 37888 B
#define SMEM_DYN (2*STAGEB)      // 75776 B
#define GITERS (DD/BKC)          // 32

__global__ __launch_bounds__(256) void gemm_bf16x3(
    const u16* __restrict__ Ah_, const u16* __restrict__ Al_, Cfg cfg)
{
    extern __shared__ char dsm[];
    uint32_t base;
    asm("{ .reg .u64 t; cvta.to.shared.u64 t, %1; cvt.u32.u64 %0, t; }"
        : "=r"(base) : "l"(dsm));

    const int tid  = threadIdx.x;
    const int lane = tid & 31;
    const int warp = tid >> 5;
    const int wm   = warp >> 2;       // 0..1
    const int wn   = warp & 3;        // 0..3

    const int bx = blockIdx.x;
    int seg = bx >> 3; if (seg > 3) seg = 3;
    const Seg sg = cfg.s[seg];
    const int col0 = (bx - seg * 8) * 128;
    const int bm   = blockIdx.y * 128;
    const int ldn  = sg.ldn;

    // ---- fragment smem offsets (stage-relative) ----
    const uint32_t aoff = (uint32_t)((wm*64 + (lane & 15)) * (A_ROW*2) + (lane >> 4) * 16);
    const uint32_t boff = (uint32_t)(2*ASZ + (lane & 15) * (B_ROW*2) + (lane >> 4) * 16 + wn * 64);

    float acc[4][4][4];
    #pragma unroll
    for (int mt = 0; mt < 4; mt++)
        #pragma unroll
        for (int nt = 0; nt < 4; nt++)
            #pragma unroll
            for (int r = 0; r < 4; r++) acc[mt][nt][r] = 0.f;

    // ---- loader: one k-chunk (128x32 A hi/lo + 32x128 B hi/lo) ----
    auto load_chunk = [&](int it, int st) {
        const uint32_t sb = base + st * STAGEB;
        const int kt = it * BKC;
        #pragma unroll
        for (int i = 0; i < 2; i++) {
            const int row = tid >> 1;
            const int c16 = (tid & 1) * 2 + i;       // 0..3
            const uint32_t so = row * (A_ROW*2) + c16 * 16;
            const size_t go = (size_t)(bm + row) * DD + kt + c16 * 8;
            CPA16(sb + so,        Ah_ + go);
            CPA16(sb + ASZ + so,  Al_ + go);
        }
        #pragma unroll
        for (int i = 0; i < 2; i++) {
            const int row = (tid >> 4) + 16 * i;     // 0..31
            const int c16 = tid & 15;
            const uint32_t so = 2*ASZ + row * (B_ROW*2) + c16 * 16;
            const size_t go = (size_t)(kt + row) * ldn + col0 + c16 * 8;
            CPA16(sb + so,        sg.wh + go);
            CPA16(sb + BSZ + so,  sg.wl + go);
        }
    };

    load_chunk(0, 0);
    asm volatile("cp.async.commit_group;");

    for (int it = 0; it < GITERS; ++it) {
        if (it + 1 < GITERS) load_chunk(it + 1, (it + 1) & 1);
        asm volatile("cp.async.commit_group;");
        asm volatile("cp.async.wait_group 1;");
        __syncthreads();

        const uint32_t sb = base + (it & 1) * STAGEB;
        #pragma unroll
        for (int ks = 0; ks < 2; ks++) {
            const uint32_t bAdH = sb + boff + ks * (16 * B_ROW * 2);
            uint32_t bh[8], bl[8];
            LDSM4T(&bh[0], bAdH);
            LDSM4T(&bh[4], bAdH + 32);
            LDSM4T(&bl[0], bAdH + BSZ);
            LDSM4T(&bl[4], bAdH + BSZ + 32);

            #pragma unroll
            for (int mt = 0; mt < 4; mt++) {
                const uint32_t aAd = sb + aoff + mt * (16 * A_ROW * 2) + ks * 32;
                uint32_t ah[4], al[4];
                LDSM4(ah, aAd);
                LDSM4(al, aAd + ASZ);
                #pragma unroll
                for (int nt = 0; nt < 4; nt++) {
                    MMA_BF16(acc[mt][nt], ah, &bh[nt*2]);
                    MMA_BF16(acc[mt][nt], ah, &bl[nt*2]);
                    MMA_BF16(acc[mt][nt], al, &bh[nt*2]);
                }
            }
        }
        __syncthreads();
    }

    // epilogue: bias (+ optional ReLU)
    const int g = lane >> 2;
    const int t = lane & 3;
    #pragma unroll
    for (int mt = 0; mt < 4; mt++) {
        const int r0 = bm + wm*64 + mt*16 + g;
        #pragma unroll
        for (int nt = 0; nt < 4; nt++) {
            const int cW = col0 + wn*32 + nt*8 + 2*t;
            const float b0 = sg.bias[cW], b1 = sg.bias[cW + 1];
            float v0 = acc[mt][nt][0] + b0;
            float v1 = acc[mt][nt][1] + b1;
            float v2 = acc[mt][nt][2] + b0;
            float v3 = acc[mt][nt][3] + b1;
            if (sg.relu) {
                v0 = fmaxf(v0, 0.f); v1 = fmaxf(v1, 0.f);
                v2 = fmaxf(v2, 0.f); v3 = fmaxf(v3, 0.f);
            }
            *(float2*)(sg.c + (size_t)r0 * ldn + cW)       = make_float2(v0, v1);
            *(float2*)(sg.c + (size_t)(r0 + 8) * ldn + cW) = make_float2(v2, v3);
        }
    }
}

// ---------------- indexer layer 2: imp[r] = hidden[r,:] . Ws2 ------------------
__global__ void indexer2_kernel(const float* __restrict__ hidden,
                                const float* __restrict__ Ws2)
{
    const int gw   = (blockIdx.x * blockDim.x + threadIdx.x) >> 5;
    const int lane = threadIdx.x & 31;
    if (gw >= MTOT) return;
    const float* hrow = hidden + (size_t)gw * (DD/2);
    float p = 0.f;
    #pragma unroll 4
    for (int c = lane; c < DD/2; c += 32) p = fmaf(hrow[c], Ws2[c], p);
    #pragma unroll
    for (int o = 16; o; o >>= 1) p += __shfl_xor_sync(0xffffffffu, p, o);
    if (lane == 0) g_imp[gw] = p;
}

// ---------------- top-K per batch: packed-key tournament, 1024 threads ---------
__global__ __launch_bounds__(1024) void topk_kernel()
{
    const int b   = blockIdx.x;
    const int tid = threadIdx.x;
    const int lane = tid & 31;
    const int wid  = tid >> 5;
    __shared__ u64 warpmax[32];
    __shared__ u64 best;

    auto mk = [](float v, int i) -> u64 {
        uint32_t u = __float_as_uint(v);
        u ^= (u >> 31) ? 0xFFFFFFFFu : 0x80000000u;
        return ((u64)u << 32) | (uint32_t)(SB - 1 - i);
    };
    u64 k0 = mk(g_imp[b*SB + tid],        tid);
    u64 k1 = mk(g_imp[b*SB + tid + 1024], tid + 1024);
    g_sel[b*SB + tid] = 0;
    g_sel[b*SB + tid + 1024] = 0;
    __syncthreads();

    for (int t = 0; t < KSEL; t++) {
        u64 m = k0 > k1 ? k0 : k1;
        #pragma unroll
        for (int o = 16; o; o >>= 1) {
            u64 x = __shfl_xor_sync(0xffffffffu, m, o);
            if (x > m) m = x;
        }
        if (lane == 0) warpmax[wid] = m;
        __syncthreads();
        if (tid < 32) {
            u64 w = warpmax[tid];
            #pragma unroll
            for (int o = 16; o; o >>= 1) {
                u64 x = __shfl_xor_sync(0xffffffffu, w, o);
                if (x > w) w = x;
            }
            if (tid == 0) best = w;
        }
        __syncthreads();
        const u64 bk = best;
        if (tid == 0) {
            const int idx = SB - 1 - (int)(bk & 0xFFFFFFFFu);
            g_idx[b*KSEL + t] = idx;
            g_sel[b*SB + idx] = 1;
        }
        if (k0 == bk) k0 = 0;
        if (k1 == bk) k1 = 0;
        __syncthreads();
    }
}

// ---------------- gather selected K/V rows into compact [B, KSEL, D] -----------
__global__ void gather_kv_kernel()
{
    const int b = blockIdx.x >> 4;
    const int j = blockIdx.x & 15;
    const int src = g_idx[b*KSEL + j];
    const float4* kr = (const float4*)(g_k + (size_t)(b*SB + src) * DD);
    const float4* vr = (const float4*)(g_v + (size_t)(b*SB + src) * DD);
    float4* kd = (float4*)(g_ksel + (size_t)(b*KSEL + j) * DD);
    float4* vd = (float4*)(g_vsel + (size_t)(b*KSEL + j) * DD);
    kd[threadIdx.x] = kr[threadIdx.x];
    vd[threadIdx.x] = vr[threadIdx.x];
}

// ---------------- sparse attention: non-selected query rows --------------------
// Writes att directly as bf16 hi/lo (feeds the Wo GEMM).
__global__ __launch_bounds__(256) void sparse_attn_kernel()
{
    const int lane = threadIdx.x & 31;
    const int gw   = (blockIdx.x * blockDim.x + threadIdx.x) >> 5;
    const int b = gw / (SB*HH);
    const int r = gw % (SB*HH);
    const int s = r / HH;
    const int h = r % HH;
    if (g_sel[b*SB + s]) return;   // warp-uniform

    const float* qrow = g_q + (size_t)(b*SB + s)*DD + h*DH;
    const float q0 = qrow[lane], q1 = qrow[lane + 32];

    float sc[KSEL];
    #pragma unroll
    for (int j = 0; j < KSEL; j++) {
        const float* kr = g_ksel + (size_t)(b*KSEL + j)*DD + h*DH;
        float p = q0*kr[lane] + q1*kr[lane + 32];
        #pragma unroll
        for (int o = 16; o; o >>= 1) p += __shfl_xor_sync(0xffffffffu, p, o);
        sc[j] = p * 0.125f;
    }
    float mx = -INFINITY;
    #pragma unroll
    for (int j = 0; j < KSEL; j++) mx = fmaxf(mx, sc[j]);
    float sum = 0.f;
    #pragma unroll
    for (int j = 0; j < KSEL; j++) { sc[j] = __expf(sc[j] - mx); sum += sc[j]; }
    const float inv = 1.f / sum;

    float o0 = 0.f, o1 = 0.f;
    #pragma unroll
    for (int j = 0; j < KSEL; j++) {
        const float* vr = g_vsel + (size_t)(b*KSEL + j)*DD + h*DH;
        o0 = fmaf(sc[j], vr[lane],      o0);
        o1 = fmaf(sc[j], vr[lane + 32], o1);
    }
    const size_t off = (size_t)(b*SB + s)*DD + h*DH;
    u16 h0, l0, h1, l1;
    bsplit(o0 * inv, h0, l0);
    bsplit(o1 * inv, h1, l1);
    g_ath[off + lane]      = h0;  g_atl[off + lane]      = l0;
    g_ath[off + lane + 32] = h1;  g_atl[off + lane + 32] = l1;
}

// ---------------- dense attention: the KSEL selected query rows ----------------
__global__ __launch_bounds__(256) void dense_attn_kernel()
{
    const int bi = blockIdx.x;
    const int b  = bi / (HH*KSEL);
    const int h  = (bi / KSEL) % HH;
    const int jq = bi % KSEL;
    const int s  = g_idx[b*KSEL + jq];

    __shared__ float qs[DH];
    __shared__ float sc[SB];
    __shared__ float red[256];
    __shared__ float part[4][DH];

    const int tid  = threadIdx.x;
    const int lane = tid & 31;
    const int w    = tid >> 5;

    if (tid < DH) qs[tid] = g_q[(size_t)(b*SB + s)*DD + h*DH + tid];
    __syncthreads();
    const float q0 = qs[lane], q1 = qs[lane + 32];

    for (int j = w; j < SB; j += 8) {
        const float* kr = g_k + (size_t)(b*SB + j)*DD + h*DH;
        float p = q0*kr[lane] + q1*kr[lane + 32];
        #pragma unroll
        for (int o = 16; o; o >>= 1) p += __shfl_xor_sync(0xffffffffu, p, o);
        if (lane == 0) sc[j] = p * 0.125f;
    }
    __syncthreads();

    float mx = -INFINITY;
    for (int j = tid; j < SB; j += 256) mx = fmaxf(mx, sc[j]);
    red[tid] = mx; __syncthreads();
    for (int st = 128; st; st >>= 1) {
        if (tid < st) red[tid] = fmaxf(red[tid], red[tid + st]);
        __syncthreads();
    }
    mx = red[0];
    __syncthreads();

    float lsum = 0.f;
    for (int j = tid; j < SB; j += 256) {
        float e = __expf(sc[j] - mx);
        sc[j] = e;
        lsum += e;
    }
    red[tid] = lsum; __syncthreads();
    for (int st = 128; st; st >>= 1) {
        if (tid < st) red[tid] += red[tid + st];
        __syncthreads();
    }
    const float inv = 1.f / red[0];

    const int d = tid & 63;
    const int c = tid >> 6;
    float acc = 0.f;
    const int j0 = c * (SB/4), j1 = j0 + (SB/4);
    for (int j = j0; j < j1; j++)
        acc = fmaf(sc[j], g_v[(size_t)(b*SB + j)*DD + h*DH + d], acc);
    part[c][d] = acc;
    __syncthreads();
    if (tid < DH) {
        float r = (part[0][tid] + part[1][tid] + part[2][tid] + part[3][tid]) * inv;
        u16 hb, lb; bsplit(r, hb, lb);
        const size_t off = (size_t)(b*SB + s)*DD + h*DH + tid;
        g_ath[off] = hb;
        g_atl[off] = lb;
    }
}

// ---------------- launch -------------------------------------------------------
extern "C" void kernel_launch(void* const* d_in, const int* in_sizes, int n_in,
                              void* d_out, int out_size)
{
    const float* x   = (const float*)d_in[0];
    const float* bq  = (const float*)d_in[2];
    const float* bk  = (const float*)d_in[4];
    const float* bv  = (const float*)d_in[6];
    const float* bo  = (const float*)d_in[8];
    const float* bs1 = (const float*)d_in[10];
    const float* Ws2 = (const float*)d_in[11];
    float* out = (float*)d_out;

    float *q, *k, *v, *hidden;
    cudaGetSymbolAddress((void**)&q,      g_q);
    cudaGetSymbolAddress((void**)&k,      g_k);
    cudaGetSymbolAddress((void**)&v,      g_v);
    cudaGetSymbolAddress((void**)&hidden, g_hidden);

    u16 *xh, *xl, *wqh, *wql, *wkh, *wkl, *wvh, *wvl;
    u16 *ws1h, *ws1l, *woh, *wol, *ath, *atl;
    cudaGetSymbolAddress((void**)&xh,   g_xh);
    cudaGetSymbolAddress((void**)&xl,   g_xl);
    cudaGetSymbolAddress((void**)&wqh,  g_wqh);
    cudaGetSymbolAddress((void**)&wql,  g_wql);
    cudaGetSymbolAddress((void**)&wkh,  g_wkh);
    cudaGetSymbolAddress((void**)&wkl,  g_wkl);
    cudaGetSymbolAddress((void**)&wvh,  g_wvh);
    cudaGetSymbolAddress((void**)&wvl,  g_wvl);
    cudaGetSymbolAddress((void**)&ws1h, g_ws1h);
    cudaGetSymbolAddress((void**)&ws1l, g_ws1l);
    cudaGetSymbolAddress((void**)&woh,  g_woh);
    cudaGetSymbolAddress((void**)&wol,  g_wol);
    cudaGetSymbolAddress((void**)&ath,  g_ath);
    cudaGetSymbolAddress((void**)&atl,  g_atl);

    cudaFuncSetAttribute(gemm_bf16x3, cudaFuncAttributeMaxDynamicSharedMemorySize, SMEM_DYN);

    dim3 t256(256);

    // 1. convert x + all weights to bf16 hi/lo
    convert_inputs<<<1024, t256>>>(x, (const float*)d_in[1], (const float*)d_in[3],
                                   (const float*)d_in[5], (const float*)d_in[9],
                                   (const float*)d_in[7]);

    // 2. fused QKV + indexer-L1 GEMM (bf16x3 tensor cores, BK=32 pipeline)
    Cfg cfg1;
    cfg1.s[0] = {wqh,  wql,  bq,  q,      DD,   0};
    cfg1.s[1] = {wkh,  wkl,  bk,  k,      DD,   0};
    cfg1.s[2] = {wvh,  wvl,  bv,  v,      DD,   0};
    cfg1.s[3] = {ws1h, ws1l, bs1, hidden, DD/2, 1};
    gemm_bf16x3<<<dim3(28, 32), t256, SMEM_DYN>>>(xh, xl, cfg1);

    // 3. indexer layer 2 -> importance logits (sigmoid skipped; monotonic)
    indexer2_kernel<<<(MTOT*32 + 255)/256, t256>>>(hidden, Ws2);

    // 4. top-k + gather
    topk_kernel<<<NB, 1024>>>();
    gather_kv_kernel<<<NB*KSEL, t256>>>();

    // 5. attention (writes att as bf16 hi/lo directly)
    sparse_attn_kernel<<<(NB*SB*HH)/8, t256>>>();
    dense_attn_kernel<<<NB*HH*KSEL, t256>>>();

    // 6. output projection -> d_out (bf16x3 tensor cores)
    Cfg cfg2;
    cfg2.s[0] = {woh, wol, bo, out, DD, 0};
    cfg2.s[1] = cfg2.s[0];
    cfg2.s[2] = cfg2.s[0];
    cfg2.s[3] = cfg2.s[0];
    gemm_bf16x3<<<dim3(8, 32), t256, SMEM_DYN>>>(ath, atl, cfg2);
}